// round 17
// baseline (speedup 1.0000x reference)
#include <cuda_runtime.h>
#include <cuda_fp16.h>
#include <cstdint>

// ---------------------------------------------------------------------------
// MaxViT3D MHSA (round 17): fp16 mma pipeline.
//   vs round 16 (236.0us): GEMM fragment loads via ldmatrix.x4
//   (8 smem instructions per warp-k16 instead of 32; same bytes).
//   Tests LSU-instruction-issue vs crossbar-bytes as the GEMM limiter.
//   Attention + prep byte-identical to round 16.
// ---------------------------------------------------------------------------

#define NWIN 128
#define NT   343
#define NTP  352
#define NTB  352
#define D    256
#define H    8
#define DH   32

// scratch
__device__ __half g_qkvh  [(size_t)NWIN * NT * (3 * D)];
__device__ __half g_ctxh  [(size_t)NWIN * NT * D];
__device__ __half g_xh    [(size_t)NWIN * NT * D];
__device__ __half g_wqkvTh[(size_t)(3 * D) * D];   // W_qkv^T [768][256] K-major
__device__ __half g_woutTh[(size_t)D * D];         // W_out^T [256][256] K-major
__device__ __half g_biash [(size_t)H * NT * NTB];

// ---------------------------------------------------------------------------
// helpers
// ---------------------------------------------------------------------------
__device__ __forceinline__ void mma16(float* c, const unsigned* a,
                                      unsigned b0, unsigned b1) {
    asm volatile(
        "mma.sync.aligned.m16n8k16.row.col.f32.f16.f16.f32 "
        "{%0,%1,%2,%3},{%4,%5,%6,%7},{%8,%9},{%0,%1,%2,%3};"
        : "+f"(c[0]), "+f"(c[1]), "+f"(c[2]), "+f"(c[3])
        : "r"(a[0]), "r"(a[1]), "r"(a[2]), "r"(a[3]), "r"(b0), "r"(b1));
}

__device__ __forceinline__ unsigned smem_u32(const void* p) {
    unsigned r;
    asm("{.reg .u64 t; cvta.to.shared.u64 t, %1; cvt.u32.u64 %0, t;}"
        : "=r"(r) : "l"(p));
    return r;
}

__device__ __forceinline__ void ldsm4(unsigned& r0, unsigned& r1,
                                      unsigned& r2, unsigned& r3,
                                      unsigned addr) {
    asm volatile(
        "ldmatrix.sync.aligned.m8n8.x4.shared.b16 {%0,%1,%2,%3}, [%4];"
        : "=r"(r0), "=r"(r1), "=r"(r2), "=r"(r3) : "r"(addr));
}

__device__ __forceinline__ void cpa16(unsigned dst, const void* src) {
    asm volatile("cp.async.ca.shared.global [%0], [%1], 16;" :: "r"(dst), "l"(src));
}
#define CP_COMMIT() asm volatile("cp.async.commit_group;")

// ---------------------------------------------------------------------------
// fused prep kernel (unchanged)
// ---------------------------------------------------------------------------
#define PREP_XB 10976
#define PREP_QB 768
#define PREP_OB 256
#define PREP_BB 3773
#define PREP_GRID (PREP_XB + PREP_QB + PREP_OB + PREP_BB)

__global__ void prep_kernel(const float4* __restrict__ x,
                            const float* __restrict__ wqkv,
                            const float* __restrict__ wout,
                            const float* __restrict__ table) {
    const int b = blockIdx.x;
    if (b < PREP_XB) {
        int i = b * 256 + threadIdx.x;
        float4 v = x[i];
        __half2 h0 = __floats2half2_rn(v.x, v.y);
        __half2 h1 = __floats2half2_rn(v.z, v.w);
        ((uint2*)g_xh)[i] = make_uint2(*(unsigned*)&h0, *(unsigned*)&h1);
    } else if (b < PREP_XB + PREP_QB) {
        int idx = (b - PREP_XB) * 256 + threadIdx.x;
        int n = idx >> 8, k = idx & 255;
        g_wqkvTh[idx] = __float2half_rn(wqkv[k * (3 * D) + n]);
    } else if (b < PREP_XB + PREP_QB + PREP_OB) {
        int idx = (b - PREP_XB - PREP_QB) * 256 + threadIdx.x;
        int n = idx >> 8, k = idx & 255;
        g_woutTh[idx] = __float2half_rn(wout[k * D + n]);
    } else {
        int idx = (b - PREP_XB - PREP_QB - PREP_OB) * 256 + threadIdx.x;
        int h = idx / (NT * NTB);
        int r = idx - h * (NT * NTB);
        int i = r / NTB;
        int j = r - i * NTB;
        float v = 0.0f;
        if (j < NT) {
            int i1 = i / 49, i2 = (i / 7) % 7, i3 = i % 7;
            int j1 = j / 49, j2 = (j / 7) % 7, j3 = j % 7;
            int rel = ((i1 - j1 + 6) * 13 + (i2 - j2 + 6)) * 13 + (i3 - j3 + 6);
            v = table[rel * H + h];
        }
        g_biash[idx] = __float2half_rn(v);
    }
}

// ---------------------------------------------------------------------------
// fp16 GEMM: 128x128 CTA tile, 4 warps of 64x64 (2x2 grid), BK=32,
// 2-stage cp.async, static smem, ldmatrix.x4 fragment loads. 128 threads.
// LGH=40 halfs (80B pitch) -> 8 ldsm row addresses distinct mod 128B.
// ---------------------------------------------------------------------------
#define LGH 40   // smem row stride in halfs

__device__ __forceinline__ void stage32_128(unsigned dstBase,
                                            const __half* __restrict__ gsrc) {
    const int tid = threadIdx.x;   // 128 threads
#pragma unroll
    for (int i = 0; i < 4; i++) {
        int id  = tid + i * 128;
        int row = id >> 2;
        int gc  = (id & 3) * 8;            // 8 halfs = 16B granule
        cpa16(dstBase + (unsigned)(row * LGH + gc) * 2,
              gsrc + (size_t)row * 256 + gc);
    }
}

template <bool HALF_OUT>
__device__ __forceinline__ void fp16_gemm_body(const __half* __restrict__ Ag,
                                               const __half* __restrict__ Bg,
                                               float* __restrict__ Cf,
                                               __half* __restrict__ Ch,
                                               int Ngl) {
    __shared__ __half As[2][128 * LGH];
    __shared__ __half Bs[2][128 * LGH];

    const int tid  = threadIdx.x;
    const int warp = tid >> 5, lane = tid & 31;
    const int g = lane >> 2, t = lane & 3;
    const int wm = warp >> 1, wn = warp & 1;    // 2x2 warp grid, 64x64 tiles

    // ldmatrix lane addressing: 4 8x8 matrices per x4
    const int mrow = lane & 7;                  // row within 8x8 matrix
    const int msel = lane >> 3;                 // matrix index 0..3
    const int lrow = (msel & 1) * 8 + mrow;     // row within 16x16 tile
    const int lcol = (msel >> 1) * 8;           // half-col within 16-wide k

    const int rowBase = blockIdx.y * 128;
    const int colBase = blockIdx.x * 128;

    const __half* Ab = Ag + (size_t)rowBase * 256;
    const __half* Bb = Bg + (size_t)colBase * 256;

    const unsigned asb0 = smem_u32(&As[0][0]);
    const unsigned bsb0 = smem_u32(&Bs[0][0]);
    const unsigned bufBytes = 128 * LGH * 2;

    // lane-invariant fragment base offsets (bytes)
    const unsigned aoff = (unsigned)((wm * 64 + lrow) * LGH + lcol) * 2;
    const unsigned boff = (unsigned)((wn * 64 + lrow) * LGH + lcol) * 2;

    float acc[4][8][4];
#pragma unroll
    for (int mt = 0; mt < 4; mt++)
#pragma unroll
        for (int nt = 0; nt < 8; nt++)
#pragma unroll
            for (int i = 0; i < 4; i++) acc[mt][nt][i] = 0.0f;

    stage32_128(asb0, Ab);
    stage32_128(bsb0, Bb);
    CP_COMMIT();

    const int iters = 256 / 32;   // 8
    for (int it = 0; it < iters; it++) {
        asm volatile("cp.async.wait_group 0;" ::: "memory");
        __syncthreads();
        if (it + 1 < iters) {
            int nb = (it + 1) & 1;
            stage32_128(asb0 + nb * bufBytes, Ab + (it + 1) * 32);
            stage32_128(bsb0 + nb * bufBytes, Bb + (it + 1) * 32);
            CP_COMMIT();
        }
        const unsigned abase = asb0 + (it & 1) * bufBytes + aoff;
        const unsigned bbase = bsb0 + (it & 1) * bufBytes + boff;

#pragma unroll
        for (int ks = 0; ks < 32; ks += 16) {
            unsigned a[4][4], b[8][2];
#pragma unroll
            for (int mt = 0; mt < 4; mt++)
                ldsm4(a[mt][0], a[mt][1], a[mt][2], a[mt][3],
                      abase + (unsigned)(mt * 16 * LGH + ks) * 2);
#pragma unroll
            for (int np = 0; np < 4; np++) {
                unsigned r0, r1, r2, r3;
                ldsm4(r0, r1, r2, r3,
                      bbase + (unsigned)(np * 16 * LGH + ks) * 2);
                b[2 * np][0]     = r0;
                b[2 * np + 1][0] = r1;
                b[2 * np][1]     = r2;
                b[2 * np + 1][1] = r3;
            }
#pragma unroll
            for (int mt = 0; mt < 4; mt++)
#pragma unroll
                for (int nt = 0; nt < 8; nt++)
                    mma16(acc[mt][nt], a[mt], b[nt][0], b[nt][1]);
        }
    }

#pragma unroll
    for (int mt = 0; mt < 4; mt++) {
#pragma unroll
        for (int nt = 0; nt < 8; nt++) {
            int r = rowBase + wm * 64 + mt * 16 + g;
            int c = colBase + wn * 64 + nt * 8 + 2 * t;
            if (HALF_OUT) {
                __half2 h0 = __floats2half2_rn(acc[mt][nt][0], acc[mt][nt][1]);
                __half2 h1 = __floats2half2_rn(acc[mt][nt][2], acc[mt][nt][3]);
                *(__half2*)(Ch + (size_t)r * Ngl + c)       = h0;
                *(__half2*)(Ch + (size_t)(r + 8) * Ngl + c) = h1;
            } else {
                *(float2*)(Cf + (size_t)r * Ngl + c) =
                    make_float2(acc[mt][nt][0], acc[mt][nt][1]);
                *(float2*)(Cf + (size_t)(r + 8) * Ngl + c) =
                    make_float2(acc[mt][nt][2], acc[mt][nt][3]);
            }
        }
    }
}

__global__ __launch_bounds__(128)
void k_gemm_qkv() {
    fp16_gemm_body<true>(g_xh, g_wqkvTh, nullptr, g_qkvh, 3 * D);
}

__global__ __launch_bounds__(128)
void k_gemm_out(float* __restrict__ out) {
    fp16_gemm_body<false>(g_ctxh, g_woutTh, out, nullptr, D);
}

// ---------------------------------------------------------------------------
// attention (EXACT round-14/15/16 body)
// ---------------------------------------------------------------------------
#define LDKH 40
#define LDVH 360
#define LDPH 24
#define AWARPS 11
#define ATHREADS (AWARPS * 32)

__global__ __launch_bounds__(ATHREADS)
void attn_kernel() {
    const int win = blockIdx.x;
    const int h   = blockIdx.y;

    extern __shared__ __half smh[];
    __half* ks = smh;                         // NTP*LDKH
    __half* vt = ks + NTP * LDKH;             // 32*LDVH
    __half* pb = vt + 32 * LDVH;              // AWARPS*16*LDPH

    const int tid  = threadIdx.x;
    const int warp = tid >> 5, lane = tid & 31;
    const int g = lane >> 2, t = lane & 3;

    const __half* baseh = g_qkvh + (size_t)win * NT * (3 * D);

    for (int idx = tid; idx < NTP * DH; idx += ATHREADS) {
        int j = idx >> 5, c = idx & 31;
        __half kv = __float2half_rn(0.0f), vv = kv;
        if (j < NT) {
            const __half* row = baseh + (size_t)j * (3 * D) + h * DH;
            kv = row[D + c];
            vv = row[2 * D + c];
        }
        ks[j * LDKH + c] = kv;
        vt[c * LDVH + j] = vv;
    }
    __syncthreads();

    const float scale = 0.17677669529663687f;
    const __half* bh = g_biash + (size_t)h * NT * NTB;
    __half* pw = pb + warp * 16 * LDPH;

    for (int qt = warp; qt < 22; qt += AWARPS) {
        const int i0 = qt * 16;
        const int r1 = i0 + g, r2 = r1 + 8;
        const int r1c = r1 < NT ? r1 : NT - 1;
        const int r2c = r2 < NT ? r2 : NT - 1;

        unsigned qa[2][4];
        const __half* q1p = baseh + (size_t)r1c * (3 * D) + h * DH;
        const __half* q2p = baseh + (size_t)r2c * (3 * D) + h * DH;
#pragma unroll
        for (int kk = 0; kk < 2; kk++) {
            qa[kk][0] = *(const unsigned*)(q1p + kk * 16 + 2 * t);
            qa[kk][1] = *(const unsigned*)(q2p + kk * 16 + 2 * t);
            qa[kk][2] = *(const unsigned*)(q1p + kk * 16 + 2 * t + 8);
            qa[kk][3] = *(const unsigned*)(q2p + kk * 16 + 2 * t + 8);
        }

        float o[4][4];
#pragma unroll
        for (int ct = 0; ct < 4; ct++)
#pragma unroll
            for (int i = 0; i < 4; i++) o[ct][i] = 0.0f;
        float l1 = 0.0f, l2 = 0.0f;

        const __half* b1p = bh + (size_t)r1c * NTB;
        const __half* b2p = bh + (size_t)r2c * NTB;

        for (int cc = 0; cc < 22; cc++) {
            const int j0 = cc * 16;

            float s0[4] = {0, 0, 0, 0}, s1[4] = {0, 0, 0, 0};
#pragma unroll
            for (int kk = 0; kk < 2; kk++) {
                unsigned b0a = *(const unsigned*)&ks[(j0 + g)     * LDKH + kk * 16 + 2 * t];
                unsigned b0b = *(const unsigned*)&ks[(j0 + g)     * LDKH + kk * 16 + 2 * t + 8];
                unsigned b1a = *(const unsigned*)&ks[(j0 + 8 + g) * LDKH + kk * 16 + 2 * t];
                unsigned b1b = *(const unsigned*)&ks[(j0 + 8 + g) * LDKH + kk * 16 + 2 * t + 8];
                mma16(s0, qa[kk], b0a, b0b);
                mma16(s1, qa[kk], b1a, b1b);
            }

            const int c0 = j0 + 2 * t;
            float2 b1a = __half22float2(*(const __half2*)(b1p + c0));
            float2 b1b = __half22float2(*(const __half2*)(b1p + c0 + 8));
            float2 b2a = __half22float2(*(const __half2*)(b2p + c0));
            float2 b2b = __half22float2(*(const __half2*)(b2p + c0 + 8));

            float p1[4], p2[4];
            p1[0] = (c0     < NT) ? __expf(fmaf(s0[0], scale, b1a.x)) : 0.0f;
            p1[1] = (c0 + 1 < NT) ? __expf(fmaf(s0[1], scale, b1a.y)) : 0.0f;
            p1[2] = (c0 + 8 < NT) ? __expf(fmaf(s1[0], scale, b1b.x)) : 0.0f;
            p1[3] = (c0 + 9 < NT) ? __expf(fmaf(s1[1], scale, b1b.y)) : 0.0f;
            p2[0] = (c0     < NT) ? __expf(fmaf(s0[2], scale, b2a.x)) : 0.0f;
            p2[1] = (c0 + 1 < NT) ? __expf(fmaf(s0[3], scale, b2a.y)) : 0.0f;
            p2[2] = (c0 + 8 < NT) ? __expf(fmaf(s1[2], scale, b2b.x)) : 0.0f;
            p2[3] = (c0 + 9 < NT) ? __expf(fmaf(s1[3], scale, b2b.y)) : 0.0f;

            l1 += p1[0] + p1[1] + p1[2] + p1[3];
            l2 += p2[0] + p2[1] + p2[2] + p2[3];

            *(__half2*)&pw[g * LDPH + 2 * t]           = __floats2half2_rn(p1[0], p1[1]);
            *(__half2*)&pw[g * LDPH + 2 * t + 8]       = __floats2half2_rn(p1[2], p1[3]);
            *(__half2*)&pw[(g + 8) * LDPH + 2 * t]     = __floats2half2_rn(p2[0], p2[1]);
            *(__half2*)&pw[(g + 8) * LDPH + 2 * t + 8] = __floats2half2_rn(p2[2], p2[3]);
            __syncwarp();

            unsigned pa[4];
            pa[0] = *(const unsigned*)&pw[g * LDPH + 2 * t];
            pa[1] = *(const unsigned*)&pw[(g + 8) * LDPH + 2 * t];
            pa[2] = *(const unsigned*)&pw[g * LDPH + 2 * t + 8];
            pa[3] = *(const unsigned*)&pw[(g + 8) * LDPH + 2 * t + 8];
#pragma unroll
            for (int ct = 0; ct < 4; ct++) {
                unsigned b0 = *(const unsigned*)&vt[(ct * 8 + g) * LDVH + j0 + 2 * t];
                unsigned b1 = *(const unsigned*)&vt[(ct * 8 + g) * LDVH + j0 + 2 * t + 8];
                mma16(o[ct], pa, b0, b1);
            }
            __syncwarp();
        }

        l1 += __shfl_xor_sync(0xffffffffu, l1, 1);
        l1 += __shfl_xor_sync(0xffffffffu, l1, 2);
        l2 += __shfl_xor_sync(0xffffffffu, l2, 1);
        l2 += __shfl_xor_sync(0xffffffffu, l2, 2);
        const float inv1 = 1.0f / l1;
        const float inv2 = 1.0f / l2;

        if (r1 < NT) {
            __half* c1 = g_ctxh + ((size_t)win * NT + r1) * D + h * DH;
#pragma unroll
            for (int ct = 0; ct < 4; ct++)
                *(__half2*)(c1 + ct * 8 + 2 * t) =
                    __floats2half2_rn(o[ct][0] * inv1, o[ct][1] * inv1);
        }
        if (r2 < NT) {
            __half* c2 = g_ctxh + ((size_t)win * NT + r2) * D + h * DH;
#pragma unroll
            for (int ct = 0; ct < 4; ct++)
                *(__half2*)(c2 + ct * 8 + 2 * t) =
                    __floats2half2_rn(o[ct][2] * inv2, o[ct][3] * inv2);
        }
    }
}

// ---------------------------------------------------------------------------
// launch
// ---------------------------------------------------------------------------
extern "C" void kernel_launch(void* const* d_in, const int* in_sizes, int n_in,
                              void* d_out, int out_size) {
    const float* x     = (const float*)d_in[0];
    const float* w_qkv = (const float*)d_in[1];
    const float* w_out = (const float*)d_in[2];
    const float* table = (const float*)d_in[3];
    float* out = (float*)d_out;

    const int attn_smem = (NTP * LDKH + 32 * LDVH + AWARPS * 16 * LDPH)
                          * (int)sizeof(__half);
    static int configured = -1;
    if (configured < 0) {
        cudaFuncSetAttribute(attn_kernel,
                             cudaFuncAttributeMaxDynamicSharedMemorySize, attn_smem);
        configured = 1;
    }

    {
        prep_kernel<<<PREP_GRID, 256>>>((const float4*)x, w_qkv, w_out, table);
    }
    {
        dim3 grid(3 * D / 128, (NWIN * NT) / 128);   // (6, 343)
        k_gemm_qkv<<<grid, 128>>>();
    }
    {
        dim3 grid(NWIN, H);
        attn_kernel<<<grid, ATHREADS, attn_smem>>>();
    }
    {
        dim3 grid(D / 128, (NWIN * NT) / 128);       // (2, 343)
        k_gemm_out<<<grid, 128>>>(out);
    }
}